// round 11
// baseline (speedup 1.0000x reference)
#include <cuda_runtime.h>
#include <cstdint>

// ============================================================================
// out[b,c] = 8192 - sx[b] - sw[c] + 2*cross[b,c]
//   cross = (weighted x bits u8) @ (w bits s8)^T : M=256, N=4096, K=8192
// GEMM is at the legacy mma.sync int8 hardware rate (~2048 MAC/cyc/SM,
// proven R4-R10). R11: hide the DRAM-bound W quant under the GEMM by
// co-scheduling smem-free quant blocks in the same launch (K split in 2):
//   L0: quant x + W k-half0            (~8.5us)
//   L1: gemm(k0) CTAs 0..127  +  quant blocks 128..639 produce W k-half1
//   L2: gemm(k1) read-add-write epilogue
// Ordering via launch boundaries only; no cross-CTA sync, no atomics.
// ============================================================================

#define THRESH 0.05f

static constexpr int MDIM = 256;
static constexpr int NDIM = 4096;
static constexpr int FDIM = 4096;
static constexpr int KDIM = 8192;     // bit dim (bytes)

// ---------------- scratch (device globals) -----------------------------------
static __device__ __align__(128) uint8_t g_xa[(size_t)MDIM * KDIM]; // 2 MB
static __device__ __align__(128) uint8_t g_wb[(size_t)NDIM * KDIM]; // 32 MB
static __device__ float g_sx[MDIM];
static __device__ float g_swp[2 * NDIM];   // per-K-slice w row sums

// ---------------- PTX helpers ------------------------------------------------
__device__ __forceinline__ uint32_t smem_u32(const void* p) {
    uint32_t a;
    asm("{ .reg .u64 t; cvta.to.shared.u64 t, %1; cvt.u32.u64 %0, t; }"
        : "=r"(a) : "l"(p));
    return a;
}

__device__ __forceinline__ void cp16(uint32_t dst, const void* src) {
    asm volatile("cp.async.cg.shared.global [%0], [%1], 16;"
                 :: "r"(dst), "l"(src) : "memory");
}
#define CP_COMMIT() asm volatile("cp.async.commit_group;" ::: "memory")
#define CP_WAIT2()  asm volatile("cp.async.wait_group 2;" ::: "memory")

__device__ __forceinline__ void mma_u8s8(int32_t* c, const uint32_t* a,
                                         const uint32_t* b) {
    asm volatile(
        "mma.sync.aligned.m16n8k32.row.col.s32.u8.s8.s32 "
        "{%0,%1,%2,%3}, {%4,%5,%6,%7}, {%8,%9}, {%0,%1,%2,%3};"
        : "+r"(c[0]), "+r"(c[1]), "+r"(c[2]), "+r"(c[3])
        : "r"(a[0]), "r"(a[1]), "r"(a[2]), "r"(a[3]), "r"(b[0]), "r"(b[1]));
}

__device__ __forceinline__ void ldsm4(uint32_t& r0, uint32_t& r1, uint32_t& r2,
                                      uint32_t& r3, uint32_t addr) {
    asm volatile("ldmatrix.sync.aligned.m8n8.x4.shared.b16 {%0,%1,%2,%3}, [%4];"
                 : "=r"(r0), "=r"(r1), "=r"(r2), "=r"(r3) : "r"(addr));
}

// ---------------- quant packing ----------------------------------------------
// Feature f (mod 4): neg/pos byte weights (128,64),(32,16),(8,4),(2,1).
template <bool WEIGHTED>
__device__ __forceinline__ uint32_t qpack2(float v0, float v1, float wn0,
                                           float wp0, float wn1, float wp1,
                                           float& s) {
    uint32_t b0 = (v0 <= -THRESH) ? (uint32_t)wn0 : 0u;
    uint32_t b1 = (v0 >=  THRESH) ? (uint32_t)wp0 : 0u;
    uint32_t b2 = (v1 <= -THRESH) ? (uint32_t)wn1 : 0u;
    uint32_t b3 = (v1 >=  THRESH) ? (uint32_t)wp1 : 0u;
    s += (float)(b0 + b1 + b2 + b3);
    if (!WEIGHTED) {
        b0 = b0 ? 1u : 0u; b1 = b1 ? 1u : 0u;
        b2 = b2 ? 1u : 0u; b3 = b3 ? 1u : 0u;
    }
    return b0 | (b1 << 8) | (b2 << 16) | (b3 << 24);
}

// One warp quantizes one W row over one K-slice (2048 features).
__device__ __forceinline__ void w_slice_quant(const float* __restrict__ w,
                                              int s, int qb, int tid) {
    const int wq = tid >> 5, lane = tid & 31;
    const int row = qb * 8 + wq;                   // w row = output column
    const float4* src = (const float4*)(w + (size_t)row * FDIM + s * (FDIM / 2));
    uint2* dst = (uint2*)(void*)(g_wb + (size_t)row * KDIM + s * (KDIM / 2));
    float sum = 0.0f;
#pragma unroll 4
    for (int j = 0; j < 16; j++) {
        const int c = lane + 32 * j;               // float4 chunk in slice row
        float4 v = src[c];
        uint2 o;
        o.x = qpack2<false>(v.x, v.y, 128.f, 64.f, 32.f, 16.f, sum);
        o.y = qpack2<false>(v.z, v.w,   8.f,  4.f,  2.f,  1.f, sum);
        dst[c] = o;
    }
#pragma unroll
    for (int off = 16; off; off >>= 1)
        sum += __shfl_xor_sync(0xffffffffu, sum, off);
    if (lane == 0) g_swp[s * NDIM + row] = sum;
}

// ============================================================================
// L0: x quant (blocks 0..255) + W slice-0 quant (blocks 256..767)
// ============================================================================
__global__ void __launch_bounds__(256) quant_pre(const float* __restrict__ x,
                                                 const float* __restrict__ w) {
    const int bid = blockIdx.x;
    const int tid = threadIdx.x;
    if (bid >= MDIM) {                 // W slice 0
        w_slice_quant(w, 0, bid - MDIM, tid);
        return;
    }
    // x row quant (weighted store) + row sum
    const float4* src = (const float4*)(x + (size_t)bid * FDIM);
    uint2* dst = (uint2*)(void*)(g_xa + (size_t)bid * KDIM);
    float s = 0.0f;
    float4 v[4];
#pragma unroll
    for (int j = 0; j < 4; j++) v[j] = src[tid + j * 256];
#pragma unroll
    for (int j = 0; j < 4; j++) {
        uint2 o;
        o.x = qpack2<true>(v[j].x, v[j].y, 128.f, 64.f, 32.f, 16.f, s);
        o.y = qpack2<true>(v[j].z, v[j].w,   8.f,  4.f,  2.f,  1.f, s);
        dst[tid + j * 256] = o;
    }
    __shared__ float red[256];
    red[tid] = s;
    __syncthreads();
    for (int off = 128; off > 0; off >>= 1) {
        if (tid < off) red[tid] += red[tid + off];
        __syncthreads();
    }
    if (tid == 0) g_sx[bid] = red[0];
}

// ============================================================================
// GEMM over one K-half (R4-winner core): BM=64, BN=128, BK=128, 4 stages,
// frag double-buffer, STRIDE=144.  Blocks >= 128 (mode 0 only) quantize
// W slice 1 instead.  launch_bounds(256,2) -> regs<=128 so a quant block
// co-resides as the second block on each SM (2 x 110.6KB smem <= 228KB).
// ============================================================================

static constexpr int BM = 64;
static constexpr int BN = 128;
static constexpr int BK = 128;
static constexpr int KITERS = (KDIM / 2) / BK;  // 32 per half
static constexpr int NSTAGES = 4;
static constexpr int STRIDE = 144;
static constexpr int A_SZ = BM * STRIDE;        // 9216
static constexpr int B_SZ = BN * STRIDE;        // 18432
static constexpr int STAGE = A_SZ + B_SZ;       // 27648
static constexpr int SMEM_BYTES = NSTAGES * STAGE;  // 110592
static constexpr int NGEMM = 32 * 4;            // 128 gemm CTAs

__global__ void __launch_bounds__(256, 2)
qgemm_kernel(const float* __restrict__ w, float* __restrict__ out,
             int koff, int mode) {
    const int tid = threadIdx.x;

    if (blockIdx.x >= NGEMM) {         // producer block: quant W slice 1
        w_slice_quant(w, 1, blockIdx.x - NGEMM, tid);
        return;
    }

    extern __shared__ char smem[];
    const uint32_t sb = smem_u32(smem);
    const int wid = tid >> 5;
    const int lane = tid & 31;
    const int wm = wid & 1;
    const int wn = wid >> 1;
    const int n0 = (blockIdx.x & 31) * BN;
    const int m0 = (blockIdx.x >> 5) * BM;

    // ---- cp.async assignments: A 2/thr, B 4/thr (koff selects K half) ------
    const uint8_t* a_src[2]; uint32_t a_dst[2];
#pragma unroll
    for (int i = 0; i < 2; i++) {
        int q = tid + i * 256;
        int r = q >> 3, kc = q & 7;
        a_src[i] = g_xa + (size_t)(m0 + r) * KDIM + koff + kc * 16;
        a_dst[i] = (uint32_t)(r * STRIDE + kc * 16);
    }
    const uint8_t* b_src[4]; uint32_t b_dst[4];
#pragma unroll
    for (int i = 0; i < 4; i++) {
        int q = tid + i * 256;
        int r = q >> 3, kc = q & 7;
        b_src[i] = g_wb + (size_t)(n0 + r) * KDIM + koff + kc * 16;
        b_dst[i] = (uint32_t)(A_SZ + r * STRIDE + kc * 16);
    }
    auto load_stage = [&](int s) {
        const uint32_t base = sb + (uint32_t)(s & (NSTAGES - 1)) * STAGE;
        const int ko = s * BK;
#pragma unroll
        for (int i = 0; i < 2; i++) cp16(base + a_dst[i], a_src[i] + ko);
#pragma unroll
        for (int i = 0; i < 4; i++) cp16(base + b_dst[i], b_src[i] + ko);
    };

    // ---- ldmatrix per-lane offsets -----------------------------------------
    const int g  = lane >> 3;
    const int lr = lane & 7;
    uint32_t a_lds[2];
#pragma unroll
    for (int mf = 0; mf < 2; mf++)
        a_lds[mf] = (uint32_t)((wm * 32 + mf * 16 + lr + (g & 1) * 8) * STRIDE
                               + (g >> 1) * 16);
    uint32_t b_lds[2];
#pragma unroll
    for (int p = 0; p < 2; p++)
        b_lds[p] = (uint32_t)(A_SZ + (wn * 32 + p * 16 + lr + (g >> 1) * 8) * STRIDE
                              + (g & 1) * 16);

    int32_t acc[2][4][4];
#pragma unroll
    for (int mf = 0; mf < 2; mf++)
#pragma unroll
        for (int nf = 0; nf < 4; nf++)
#pragma unroll
            for (int r = 0; r < 4; r++) acc[mf][nf][r] = 0;

    uint32_t afr[2][2][4];   // [buf][mf][reg]
    uint32_t bfr[2][4][2];   // [buf][nf][reg]
    auto load_frags = [&](uint32_t sbase, int ks, int buf) {
        const uint32_t kb = (uint32_t)(ks * 32);
#pragma unroll
        for (int mf = 0; mf < 2; mf++)
            ldsm4(afr[buf][mf][0], afr[buf][mf][1], afr[buf][mf][2],
                  afr[buf][mf][3], sbase + a_lds[mf] + kb);
#pragma unroll
        for (int p = 0; p < 2; p++)
            ldsm4(bfr[buf][2*p][0], bfr[buf][2*p][1],
                  bfr[buf][2*p+1][0], bfr[buf][2*p+1][1],
                  sbase + b_lds[p] + kb);
    };

    // ---- prologue: 3 stages in flight --------------------------------------
#pragma unroll
    for (int s = 0; s < NSTAGES - 1; ++s) { load_stage(s); CP_COMMIT(); }

    for (int it = 0; it < KITERS; ++it) {
        CP_WAIT2();
        __syncthreads();

        const int pf = it + NSTAGES - 1;
        if (pf < KITERS) load_stage(pf);
        CP_COMMIT();

        const uint32_t sbase = sb + (uint32_t)(it & (NSTAGES - 1)) * STAGE;
        load_frags(sbase, 0, 0);
#pragma unroll
        for (int ks = 0; ks < BK / 32; ++ks) {
            const int cur = ks & 1;
            if (ks < BK / 32 - 1) load_frags(sbase, ks + 1, cur ^ 1);
#pragma unroll
            for (int mf = 0; mf < 2; mf++)
#pragma unroll
                for (int nf = 0; nf < 4; nf++)
                    mma_u8s8(acc[mf][nf], afr[cur][mf], bfr[cur][nf]);
        }
    }

    // ---- epilogue ----------------------------------------------------------
    // mode 0 (slice 0): out  = 8192 - sx[m] - swp0[c] + 2*acc
    // mode 1 (slice 1): out += -swp1[c] + 2*acc
    const float* swp = g_swp + (koff ? NDIM : 0);
#pragma unroll
    for (int mf = 0; mf < 2; mf++) {
        const int r0 = m0 + wm * 32 + mf * 16 + (lane >> 2);
        const float bx0 = mode ? 0.0f : (8192.0f - g_sx[r0]);
        const float bx1 = mode ? 0.0f : (8192.0f - g_sx[r0 + 8]);
#pragma unroll
        for (int nf = 0; nf < 4; nf++) {
            const int col = n0 + wn * 32 + nf * 8 + (lane & 3) * 2;
            const float sw0 = swp[col], sw1 = swp[col + 1];
            float* p0 = out + (size_t)r0 * NDIM + col;
            float* p1 = out + (size_t)(r0 + 8) * NDIM + col;
            float2 v0, v1;
            v0.x = bx0 - sw0 + 2.0f * (float)acc[mf][nf][0];
            v0.y = bx0 - sw1 + 2.0f * (float)acc[mf][nf][1];
            v1.x = bx1 - sw0 + 2.0f * (float)acc[mf][nf][2];
            v1.y = bx1 - sw1 + 2.0f * (float)acc[mf][nf][3];
            if (mode) {
                float2 o0 = *(float2*)p0, o1 = *(float2*)p1;
                v0.x += o0.x; v0.y += o0.y;
                v1.x += o1.x; v1.y += o1.y;
            }
            *(float2*)p0 = v0;
            *(float2*)p1 = v1;
        }
    }
}

// ============================================================================
// launcher
// ============================================================================
extern "C" void kernel_launch(void* const* d_in, const int* in_sizes, int n_in,
                              void* d_out, int out_size) {
    (void)in_sizes; (void)n_in; (void)out_size;
    const float* x = (const float*)d_in[0];   // [256, 4096]
    const float* w = (const float*)d_in[1];   // [4096, 4096]
    float* out = (float*)d_out;               // [256, 4096]

    quant_pre<<<MDIM + 512, 256>>>(x, w);     // x + W slice 0

    cudaFuncSetAttribute(qgemm_kernel,
                         cudaFuncAttributeMaxDynamicSharedMemorySize, SMEM_BYTES);
    // L1: gemm slice 0 (write) + co-scheduled quant of W slice 1
    qgemm_kernel<<<NGEMM + 512, 256, SMEM_BYTES>>>(w, out, 0, 0);
    // L2: gemm slice 1 (accumulate)
    qgemm_kernel<<<NGEMM, 256, SMEM_BYTES>>>(w, out, KDIM / 2, 1);
}

// round 13
// speedup vs baseline: 1.2442x; 1.2442x over previous
#include <cuda_runtime.h>
#include <cstdint>

// ============================================================================
// out[b,c] = 8192 - sx[b] - sw[c] + 2*cross[b,c]
//   cross = (weighted x bits u8) @ (w bits s8)^T : M=256, N=4096, K=8192
// GEMM = legacy mma.sync int8 at its accept-rate wall (~44.5us, R4-R10).
// R13 = R12 resubmission after audit (R12 "container failed twice" attributed
// to infra, matching the R1 precedent; full hang/fault audit found no issue).
// Design: W intermediate stored 1-bit PACKED (4MB not 32MB) -> quant LTS bytes
// 102->74MB (~11.5us). GEMM expands packed->s8 bytes in-SMEM (ALU idle slots),
// accumulating sw for free via brev. No cross-CTA sync anywhere.
// ============================================================================

#define THRESH 0.05f

static constexpr int MDIM = 256;
static constexpr int NDIM = 4096;
static constexpr int FDIM = 4096;
static constexpr int KDIM = 8192;          // bit dim
static constexpr int WPROW = KDIM / 8;     // 1024 packed bytes per W row

// ---------------- scratch (device globals) -----------------------------------
static __device__ __align__(128) uint8_t g_xa[(size_t)MDIM * KDIM];   // 2 MB
static __device__ __align__(128) uint8_t g_wp[(size_t)NDIM * WPROW];  // 4 MB
static __device__ float g_sx[MDIM];

// ---------------- PTX helpers ------------------------------------------------
__device__ __forceinline__ uint32_t smem_u32(const void* p) {
    uint32_t a;
    asm("{ .reg .u64 t; cvta.to.shared.u64 t, %1; cvt.u32.u64 %0, t; }"
        : "=r"(a) : "l"(p));
    return a;
}

__device__ __forceinline__ void cp16(uint32_t dst, const void* src) {
    asm volatile("cp.async.cg.shared.global [%0], [%1], 16;"
                 :: "r"(dst), "l"(src) : "memory");
}
#define CP_COMMIT() asm volatile("cp.async.commit_group;" ::: "memory")
#define CP_WAIT2()  asm volatile("cp.async.wait_group 2;" ::: "memory")

__device__ __forceinline__ void mma_u8s8(int32_t* c, const uint32_t* a,
                                         const uint32_t* b) {
    asm volatile(
        "mma.sync.aligned.m16n8k32.row.col.s32.u8.s8.s32 "
        "{%0,%1,%2,%3}, {%4,%5,%6,%7}, {%8,%9}, {%0,%1,%2,%3};"
        : "+r"(c[0]), "+r"(c[1]), "+r"(c[2]), "+r"(c[3])
        : "r"(a[0]), "r"(a[1]), "r"(a[2]), "r"(a[3]), "r"(b[0]), "r"(b[1]));
}

__device__ __forceinline__ void ldsm4(uint32_t& r0, uint32_t& r1, uint32_t& r2,
                                      uint32_t& r3, uint32_t addr) {
    asm volatile("ldmatrix.sync.aligned.m8n8.x4.shared.b16 {%0,%1,%2,%3}, [%4];"
                 : "=r"(r0), "=r"(r1), "=r"(r2), "=r"(r3) : "r"(addr));
}

// ---------------- quant packing (x side: weighted bytes) ----------------------
__device__ __forceinline__ uint32_t qpack2x(float v0, float v1, float wn0,
                                            float wp0, float wn1, float wp1,
                                            float& s) {
    uint32_t b0 = (v0 <= -THRESH) ? (uint32_t)wn0 : 0u;
    uint32_t b1 = (v0 >=  THRESH) ? (uint32_t)wp0 : 0u;
    uint32_t b2 = (v1 <= -THRESH) ? (uint32_t)wn1 : 0u;
    uint32_t b3 = (v1 >=  THRESH) ? (uint32_t)wp1 : 0u;
    s += (float)(b0 + b1 + b2 + b3);
    return b0 | (b1 << 8) | (b2 << 16) | (b3 << 24);
}

// ============================================================================
// quant kernel: blocks [0,256) -> x rows (weighted u8 + sx);
//               blocks [256, 256+4096) -> W rows packed to 1 bit/plane.
// Packed byte p of a row = planes 8p..8p+7, bit i = plane 8p+i
// (plane 2f = neg_f, 2f+1 = pos_f; in-byte weights 2^(7-i) applied in GEMM).
// ============================================================================
__global__ void __launch_bounds__(256) quant_kernel(const float* __restrict__ x,
                                                    const float* __restrict__ w) {
    const int bid = blockIdx.x;
    const int tid = threadIdx.x;
    const int lane = tid & 31;

    if (bid >= MDIM) {                         // ---- W pack: one row/block ----
        const int row = bid - MDIM;
        const float4* src = (const float4*)(w + (size_t)row * FDIM);
        uint32_t* dst = (uint32_t*)(void*)(g_wp + (size_t)row * WPROW);
#pragma unroll
        for (int j = 0; j < 4; j++) {
            const int c = tid + 256 * j;       // float4 chunk == packed byte idx
            float4 v = src[c];
            uint32_t b =
                ((v.x <= -THRESH) ? 1u : 0u)   | ((v.x >= THRESH) ? 2u : 0u) |
                ((v.y <= -THRESH) ? 4u : 0u)   | ((v.y >= THRESH) ? 8u : 0u) |
                ((v.z <= -THRESH) ? 16u : 0u)  | ((v.z >= THRESH) ? 32u : 0u) |
                ((v.w <= -THRESH) ? 64u : 0u)  | ((v.w >= THRESH) ? 128u : 0u);
            uint32_t val = b << (8 * (lane & 3));
            val |= __shfl_xor_sync(0xffffffffu, val, 1);
            val |= __shfl_xor_sync(0xffffffffu, val, 2);
            if ((lane & 3) == 0) dst[c >> 2] = val;
        }
        return;
    }

    // ---- x row quant (weighted bytes) + row sum ----------------------------
    const float4* src = (const float4*)(x + (size_t)bid * FDIM);
    uint2* dst = (uint2*)(void*)(g_xa + (size_t)bid * KDIM);
    float s = 0.0f;
    float4 v[4];
#pragma unroll
    for (int j = 0; j < 4; j++) v[j] = src[tid + j * 256];
#pragma unroll
    for (int j = 0; j < 4; j++) {
        uint2 o;
        o.x = qpack2x(v[j].x, v[j].y, 128.f, 64.f, 32.f, 16.f, s);
        o.y = qpack2x(v[j].z, v[j].w,   8.f,  4.f,  2.f,  1.f, s);
        dst[tid + j * 256] = o;
    }
    __shared__ float red[256];
    red[tid] = s;
    __syncthreads();
    for (int off = 128; off > 0; off >>= 1) {
        if (tid < off) red[tid] += red[tid + off];
        __syncthreads();
    }
    if (tid == 0) g_sx[bid] = red[0];
}

// ============================================================================
// GEMM: BM=64, BN=128, BK=128; A = 4-stage cp.async (R5 core);
// B = packed LDG -> in-SMEM bit->byte expansion, double-buffered.
// 256 thr = 8 warps 2(M) x 4(N), warp tile 32x32, STRIDE=144.
// Grid (32,4) = 128 CTAs.
// ============================================================================

static constexpr int BM = 64;
static constexpr int BN = 128;
static constexpr int BK = 128;
static constexpr int KITERS = KDIM / BK;        // 64
static constexpr int NSTAGES = 4;
static constexpr int STRIDE = 144;
static constexpr int A_SZ = BM * STRIDE;        // 9216
static constexpr int B_OFF = NSTAGES * A_SZ;    // 36864
static constexpr int B_SZ = BN * STRIDE;        // 18432
static constexpr int SMEM_BYTES = B_OFF + 2 * B_SZ;  // 73728

__global__ void __launch_bounds__(256, 1)
qgemm_kernel(float* __restrict__ out) {
    extern __shared__ char smem[];
    __shared__ float swacc[BN];

    const uint32_t sb = smem_u32(smem);
    const int tid = threadIdx.x;
    const int wid = tid >> 5;
    const int lane = tid & 31;
    const int wm = wid & 1;
    const int wn = wid >> 1;
    const int n0 = blockIdx.x * BN;
    const int m0 = blockIdx.y * BM;

    // ---- A cp.async: 2 chunks/thread ---------------------------------------
    const uint8_t* a_src[2]; uint32_t a_dst[2];
#pragma unroll
    for (int i = 0; i < 2; i++) {
        int q = tid + i * 256;
        int r = q >> 3, kc = q & 7;
        a_src[i] = g_xa + (size_t)(m0 + r) * KDIM + kc * 16;
        a_dst[i] = (uint32_t)(r * STRIDE + kc * 16);
    }
    auto load_stage = [&](int s) {
        const uint32_t base = sb + (uint32_t)(s & (NSTAGES - 1)) * A_SZ;
        const int ko = s * BK;
#pragma unroll
        for (int i = 0; i < 2; i++) cp16(base + a_dst[i], a_src[i] + ko);
    };

    // ---- B expansion: thread covers (row tid>>1, 64-byte half tid&1) -------
    const int brow = tid >> 1;
    const int h    = tid & 1;
    const uint8_t* wp_src = g_wp + (size_t)(n0 + brow) * WPROW + h * 8;
    const uint32_t bds = (uint32_t)(B_OFF + brow * STRIDE + h * 64);
    int isw = 0;
    auto expand = [&](uint2 pk, int slot) {
        char* base = smem + bds + slot * B_SZ;
        uint32_t wv[2] = { pk.x, pk.y };
#pragma unroll
        for (int wq = 0; wq < 2; wq++) {
            uint32_t o[8];
#pragma unroll
            for (int bi = 0; bi < 4; bi++) {
                uint32_t b = (wv[wq] >> (8 * bi)) & 0xFFu;
                isw += (int)(__brev(b) >> 24);          // byte-weighted bit sum
                o[2 * bi]     = ((b & 0xFu) * 0x00204081u) & 0x01010101u;
                o[2 * bi + 1] = ((b >> 4)   * 0x00204081u) & 0x01010101u;
            }
#pragma unroll
            for (int k = 0; k < 2; k++)
                *(uint4*)(base + wq * 32 + k * 16) =
                    make_uint4(o[4 * k], o[4 * k + 1], o[4 * k + 2], o[4 * k + 3]);
        }
    };

    // ---- ldmatrix per-lane offsets -----------------------------------------
    const int g  = lane >> 3;
    const int lr = lane & 7;
    uint32_t a_lds[2];
#pragma unroll
    for (int mf = 0; mf < 2; mf++)
        a_lds[mf] = (uint32_t)((wm * 32 + mf * 16 + lr + (g & 1) * 8) * STRIDE
                               + (g >> 1) * 16);
    uint32_t b_lds[2];
#pragma unroll
    for (int p = 0; p < 2; p++)
        b_lds[p] = (uint32_t)((wn * 32 + p * 16 + lr + (g >> 1) * 8) * STRIDE
                              + (g & 1) * 16);

    int32_t acc[2][4][4];
#pragma unroll
    for (int mf = 0; mf < 2; mf++)
#pragma unroll
        for (int nf = 0; nf < 4; nf++)
#pragma unroll
            for (int r = 0; r < 4; r++) acc[mf][nf][r] = 0;

    uint32_t afr[2][2][4];
    uint32_t bfr[2][4][2];
    auto load_frags = [&](uint32_t abase, uint32_t bbase, int ks, int buf) {
        const uint32_t kb = (uint32_t)(ks * 32);
#pragma unroll
        for (int mf = 0; mf < 2; mf++)
            ldsm4(afr[buf][mf][0], afr[buf][mf][1], afr[buf][mf][2],
                  afr[buf][mf][3], abase + a_lds[mf] + kb);
#pragma unroll
        for (int p = 0; p < 2; p++)
            ldsm4(bfr[buf][2*p][0], bfr[buf][2*p][1],
                  bfr[buf][2*p+1][0], bfr[buf][2*p+1][1],
                  bbase + b_lds[p] + kb);
    };

    // ---- prologue ----------------------------------------------------------
#pragma unroll
    for (int s = 0; s < NSTAGES - 1; ++s) { load_stage(s); CP_COMMIT(); }
    uint2 pk = *(const uint2*)wp_src;       // packed chunk 0
    expand(pk, 0);                          // B chunk 0 -> slot 0
    pk = *(const uint2*)(wp_src + 16);      // packed chunk 1

    // ---- mainloop ----------------------------------------------------------
    for (int it = 0; it < KITERS; ++it) {
        CP_WAIT2();
        __syncthreads();     // A stage it + B slot it&1 visible; old slots free

        if (it + 1 < KITERS) expand(pk, (it + 1) & 1);
        if (it + 2 < KITERS) pk = *(const uint2*)(wp_src + (it + 2) * 16);
        if (it + NSTAGES - 1 < KITERS) load_stage(it + NSTAGES - 1);
        CP_COMMIT();

        const uint32_t abase = sb + (uint32_t)(it & (NSTAGES - 1)) * A_SZ;
        const uint32_t bbase = sb + (uint32_t)(B_OFF + (it & 1) * B_SZ);
        load_frags(abase, bbase, 0, 0);
#pragma unroll
        for (int ks = 0; ks < BK / 32; ++ks) {
            const int cur = ks & 1;
            if (ks < BK / 32 - 1) load_frags(abase, bbase, ks + 1, cur ^ 1);
#pragma unroll
            for (int mf = 0; mf < 2; mf++)
#pragma unroll
                for (int nf = 0; nf < 4; nf++)
                    mma_u8s8(acc[mf][nf], afr[cur][mf], bfr[cur][nf]);
        }
    }

    // ---- sw: pair (tid, tid^1) covers a full W row over all chunks ---------
    const int sw2 = isw + __shfl_xor_sync(0xffffffffu, isw, 1);
    if (h == 0) swacc[brow] = (float)sw2;
    __syncthreads();

    // ---- epilogue: out = 8192 - sx[m] - sw[n] + 2*acc  (exact integers) ----
#pragma unroll
    for (int mf = 0; mf < 2; mf++) {
        const int r0 = m0 + wm * 32 + mf * 16 + (lane >> 2);
        const float bx0 = 8192.0f - g_sx[r0];
        const float bx1 = 8192.0f - g_sx[r0 + 8];
#pragma unroll
        for (int nf = 0; nf < 4; nf++) {
            const int cl = wn * 32 + nf * 8 + (lane & 3) * 2;
            const float sw0 = swacc[cl], sw1 = swacc[cl + 1];
            const int col = n0 + cl;
            float2 v0, v1;
            v0.x = bx0 - sw0 + 2.0f * (float)acc[mf][nf][0];
            v0.y = bx0 - sw1 + 2.0f * (float)acc[mf][nf][1];
            v1.x = bx1 - sw0 + 2.0f * (float)acc[mf][nf][2];
            v1.y = bx1 - sw1 + 2.0f * (float)acc[mf][nf][3];
            *(float2*)(out + (size_t)r0 * NDIM + col) = v0;
            *(float2*)(out + (size_t)(r0 + 8) * NDIM + col) = v1;
        }
    }
}

// ============================================================================
// launcher
// ============================================================================
extern "C" void kernel_launch(void* const* d_in, const int* in_sizes, int n_in,
                              void* d_out, int out_size) {
    (void)in_sizes; (void)n_in; (void)out_size;
    const float* x = (const float*)d_in[0];   // [256, 4096]
    const float* w = (const float*)d_in[1];   // [4096, 4096]
    float* out = (float*)d_out;               // [256, 4096]

    quant_kernel<<<MDIM + NDIM, 256>>>(x, w);

    cudaFuncSetAttribute(qgemm_kernel,
                         cudaFuncAttributeMaxDynamicSharedMemorySize, SMEM_BYTES);
    dim3 grid(NDIM / BN, MDIM / BM);          // (32, 4) = 128 CTAs
    qgemm_kernel<<<grid, 256, SMEM_BYTES>>>(out);
}